// round 12
// baseline (speedup 1.0000x reference)
#include <cuda_runtime.h>
#include <cuda_bf16.h>
#include <cstdint>

#define NN 50000
#define NE 600000
#define DD 128
#define NG 64
#define NTILE 391

typedef unsigned long long u64;

// ---------------- device scratch (no allocations allowed) ----------------
__device__ float g_bufA[NN * DD];
__device__ float g_bufB[NN * DD];
__device__ __nv_bfloat16 g_xH[NN * DD];
__device__ __nv_bfloat16 g_xL[NN * DD];
__device__ int g_src[NE];
__device__ int g_dst[NE];
__device__ int g_csr[NE];
__device__ int g_cnt[NN];
__device__ int g_ofs[NN + 1];
__device__ int g_fill[NN];
__device__ int g_batch[NN];
__device__ int g_bsum[64];
// [layer][WlH, WlL, WrH, WrL], each image 16384 bf16, pre-swizzled for smem
__device__ __nv_bfloat16 g_Wimg[16 * 16384];
__device__ int g_flag;  // 1 => inputs are int32, 0 => int64 (monotone, deterministic)

__device__ __forceinline__ uint32_t smem_to_u32(const void* smem_ptr) {
    uint32_t addr;
    asm("{ .reg .u64 tmp; cvta.to.shared.u64 tmp, %1; cvt.u32.u64 %0, tmp; }"
        : "=r"(addr) : "l"(smem_ptr));
    return addr;
}
__device__ __forceinline__ uint32_t pack_bf16x2(float hi_elem, float lo_elem) {
    uint32_t r;
    asm("cvt.rn.bf16x2.f32 %0, %1, %2;" : "=r"(r) : "f"(hi_elem), "f"(lo_elem));
    return r;
}
__device__ __forceinline__ void ldsm4(uint32_t* r, uint32_t addr) {
    asm volatile("ldmatrix.sync.aligned.m8n8.x4.shared.b16 {%0,%1,%2,%3}, [%4];"
                 : "=r"(r[0]), "=r"(r[1]), "=r"(r[2]), "=r"(r[3]) : "r"(addr));
}
__device__ __forceinline__ void mma16816(float* c, const uint32_t* a, uint32_t b0, uint32_t b1) {
    asm volatile(
        "mma.sync.aligned.m16n8k16.row.col.f32.bf16.bf16.f32 "
        "{%0,%1,%2,%3}, {%4,%5,%6,%7}, {%8,%9}, {%0,%1,%2,%3};"
        : "+f"(c[0]), "+f"(c[1]), "+f"(c[2]), "+f"(c[3])
        : "r"(a[0]), "r"(a[1]), "r"(a[2]), "r"(a[3]), "r"(b0), "r"(b1));
}
#define CPA16(dst, src, sz) \
    asm volatile("cp.async.cg.shared.global [%0], [%1], 16, %2;" \
                 :: "r"(dst), "l"(src), "r"(sz) : "memory")
#define CPC() asm volatile("cp.async.commit_group;" ::: "memory")
#define CPW(n) asm volatile("cp.async.wait_group %0;" :: "n"(n) : "memory")

// ---------------- setup kernels ----------------
__global__ void splitw_kernel(const float* __restrict__ Wl, const float* __restrict__ Wr) {
    int i = blockIdx.x * blockDim.x + threadIdx.x;  // < 4*2*16384
    int l = i >> 15;
    int rem = i & 32767;
    int mat = rem >> 14;
    int nk = rem & 16383;
    int n = nk >> 7, k = nk & 127;
    const float* W = mat ? Wr : Wl;
    float v = W[l * 16384 + nk];
    __nv_bfloat16 bh = __float2bfloat16(v);
    float fhi = __bfloat162float(bh);
    __nv_bfloat16 blo = __float2bfloat16(v - fhi);
    int off = n * 128 + (((k >> 3) ^ (n & 7)) << 3) + (k & 7);
    int base = (l * 4 + mat * 2) * 16384;
    g_Wimg[base + off] = bh;
    g_Wimg[base + 16384 + off] = blo;
}

// Split x_in into bf16 hi/lo images (row-major, 256B rows).
__global__ void splitx_kernel(const float4* __restrict__ x) {
    int i = blockIdx.x * blockDim.x + threadIdx.x;  // < NN*32
    if (i >= NN * 32) return;
    float4 f = x[i];
    float hx = __bfloat162float(__float2bfloat16(f.x));
    float hy = __bfloat162float(__float2bfloat16(f.y));
    float hz = __bfloat162float(__float2bfloat16(f.z));
    float hw = __bfloat162float(__float2bfloat16(f.w));
    uint2 hv, lv;
    hv.x = pack_bf16x2(f.y, f.x); hv.y = pack_bf16x2(f.w, f.z);
    lv.x = pack_bf16x2(f.y - hy, f.x - hx); lv.y = pack_bf16x2(f.w - hw, f.z - hz);
    ((uint2*)g_xH)[i] = hv;
    ((uint2*)g_xL)[i] = lv;
}

// zero counts; block 0 additionally detects int32 vs int64 edge dtype.
__global__ void zerodetect_kernel(const int* __restrict__ e) {
    int i = blockIdx.x * blockDim.x + threadIdx.x;
    if (i < NN) g_cnt[i] = 0;
    if (blockIdx.x == 0) {
        int nz = 0;
        for (int j = threadIdx.x; j < 4096; j += 256) nz |= e[2 * j + 1];
        if (nz) g_flag = 1;
    }
}

// convert edges + batch, and histogram dst degrees in one pass
__global__ void convhist_kernel(const void* __restrict__ e, const void* __restrict__ b) {
    int i = blockIdx.x * blockDim.x + threadIdx.x;
    int is32 = g_flag;
    if (i < NE) {
        int s, d;
        if (is32) {
            const int* p = (const int*)e;
            s = p[i]; d = p[NE + i];
        } else {
            const long long* p = (const long long*)e;
            s = (int)p[i]; d = (int)p[NE + i];
        }
        g_src[i] = s;
        g_dst[i] = d;
        atomicAdd(&g_cnt[d], 1);
    }
    if (i < NN) {
        g_batch[i] = is32 ? ((const int*)b)[i] : (int)((const long long*)b)[i];
    }
}

// ---- 2-pass grid-wide exclusive scan of g_cnt -> g_ofs / g_fill ----
__global__ void scan1_kernel() {
    __shared__ int wsum[32];
    int b = blockIdx.x, t = threadIdx.x;
    int idx = b * 1024 + t;
    int v = (idx < NN) ? g_cnt[idx] : 0;
    int lane = t & 31, wid = t >> 5;
    int x = v;
    #pragma unroll
    for (int d = 1; d < 32; d <<= 1) {
        int n = __shfl_up_sync(0xFFFFFFFFu, x, d);
        if (lane >= d) x += n;
    }
    if (lane == 31) wsum[wid] = x;
    __syncthreads();
    if (wid == 0) {
        int wv = wsum[lane];
        #pragma unroll
        for (int d = 1; d < 32; d <<= 1) {
            int n = __shfl_up_sync(0xFFFFFFFFu, wv, d);
            if (lane >= d) wv += n;
        }
        wsum[lane] = wv;
    }
    __syncthreads();
    int excl = (x - v) + (wid > 0 ? wsum[wid - 1] : 0);
    if (idx < NN) g_ofs[idx] = excl;
    if (t == 1023) g_bsum[b] = excl + v;  // block total
}

// pass 2: each block computes its own block offset from g_bsum and applies it.
__global__ void scan23_kernel(int nblk) {
    __shared__ int s_bsum[64];
    __shared__ int s_off;
    int b = blockIdx.x, t = threadIdx.x;
    if (t < nblk) s_bsum[t] = g_bsum[t];
    __syncthreads();
    if (t == 0) {
        int run = 0;
        for (int j = 0; j < b; j++) run += s_bsum[j];
        s_off = run;
        if (b == nblk - 1) {
            int tot = run;
            for (int j = b; j < nblk; j++) tot += s_bsum[j];
            g_ofs[NN] = tot;
        }
    }
    __syncthreads();
    int idx = b * 1024 + t;
    if (idx < NN) {
        int o = g_ofs[idx] + s_off;
        g_ofs[idx] = o;
        g_fill[idx] = o;
    }
}

__global__ void fill_kernel() {
    int i = blockIdx.x * blockDim.x + threadIdx.x;
    if (i < NE) {
        int d = g_dst[i];
        int pos = atomicAdd(&g_fill[d], 1);
        g_csr[pos] = g_src[i];
    }
}

// ---------------- fused layer kernel: gather-mean + dual GEMM + epilogue ----------------
// Per tile of 128 rows:
//   phase A: issue x-split chunk 0 cp.async; warp-per-node gather-mean from fp32 cur,
//            convert to bf16 hi/lo directly into smem (272B-stride rows, ldsm-ready)
//   phase B: 4 k-chunks: wait x chunk, 6-term mma (agg hi/lo x Wl hi/lo; x hi/lo x Wr hi/lo)
//   phase C: bias + leaky relu (+ residual), write fp32 next-x + optional bf16 split
#define W_SM 131072
#define AGG_STR 272
#define AGG_IMG 34816                 // 128 * 272
#define X_IMG 10240                   // 128 * 80
#define AGG_BASE W_SM                 // 2 images
#define X_BASE (W_SM + 2 * AGG_IMG)   // 200704, 2 images single-stage
#define SMEM_TOTAL (X_BASE + 2 * X_IMG)  // 221184

__global__ __launch_bounds__(256, 1)
void fused_kernel(const float* __restrict__ xF,
                  const __nv_bfloat16* __restrict__ xH, const __nv_bfloat16* __restrict__ xL,
                  const __nv_bfloat16* __restrict__ Wimg, const float* __restrict__ bias,
                  float* __restrict__ outF,
                  __nv_bfloat16* __restrict__ oH, __nv_bfloat16* __restrict__ oL,
                  int resid, int wsplit) {
    extern __shared__ __align__(16) char dsm[];

    const int t = threadIdx.x;
    const int lane = t & 31;
    const int wid = t >> 5;
    const int warp_m = wid >> 1;
    const int warp_n = wid & 1;
    const uint32_t w_u32 = smem_to_u32(dsm);
    const uint32_t agg_u32 = w_u32 + AGG_BASE;
    const uint32_t x_u32 = w_u32 + X_BASE;

    const char* Ximg[2] = {(const char*)xH, (const char*)xL};
    const float4* xrow = (const float4*)xF;

    // bias per-thread registers (cols this thread owns)
    float2 bv[8];
    #pragma unroll
    for (int nt = 0; nt < 8; nt++)
        bv[nt] = *(const float2*)(bias + warp_n * 64 + nt * 8 + (lane & 3) * 2);

    // stage all 4 W images: 8192 linear 16B chunks
    {
        const char* wp = (const char*)Wimg;
        #pragma unroll 8
        for (int i = t; i < 8192; i += 256)
            CPA16(w_u32 + i * 16, wp + i * 16, 16);
        CPC();
    }

    for (int tile = blockIdx.x; tile < NTILE; tile += gridDim.x) {
        const int bm = tile * 128;

        // issue x chunk 0: 2 images x 128 rows x 64B = 1024 chunks of 16B
        #pragma unroll
        for (int j = 0; j < 4; j++) {
            int ch = t + j * 256;               // < 1024
            int img = ch >> 9, rem = ch & 511;
            int row = rem >> 2, cc = rem & 3;
            int rg = bm + row;
            int ok = rg < NN;
            const char* src = Ximg[img] + (size_t)(ok ? rg : 0) * 256 + cc * 16;
            CPA16(x_u32 + img * X_IMG + row * 80 + cc * 16, src, ok ? 16 : 0);
        }
        CPC();

        // ---- gather phase: warp w handles rows [w*16, w*16+16) of this tile ----
        {
            int wrow = wid * 16;
            for (int rr = 0; rr < 16; rr++) {
                int row = bm + wrow + rr;
                int beg = 0, end = 0;
                if (row < NN) { beg = g_ofs[row]; end = g_ofs[row + 1]; }
                float4 a0 = make_float4(0.f, 0.f, 0.f, 0.f);
                float4 a1 = a0, a2 = a0, a3 = a0;
                int e = beg;
                for (; e + 4 <= end; e += 4) {
                    int s0 = g_csr[e], s1 = g_csr[e + 1], s2 = g_csr[e + 2], s3 = g_csr[e + 3];
                    float4 v0 = xrow[s0 * 32 + lane];
                    float4 v1 = xrow[s1 * 32 + lane];
                    float4 v2 = xrow[s2 * 32 + lane];
                    float4 v3 = xrow[s3 * 32 + lane];
                    a0.x += v0.x; a0.y += v0.y; a0.z += v0.z; a0.w += v0.w;
                    a1.x += v1.x; a1.y += v1.y; a1.z += v1.z; a1.w += v1.w;
                    a2.x += v2.x; a2.y += v2.y; a2.z += v2.z; a2.w += v2.w;
                    a3.x += v3.x; a3.y += v3.y; a3.z += v3.z; a3.w += v3.w;
                }
                for (; e < end; e++) {
                    int s = g_csr[e];
                    float4 v = xrow[s * 32 + lane];
                    a0.x += v.x; a0.y += v.y; a0.z += v.z; a0.w += v.w;
                }
                int c = end - beg;
                float inv = 1.0f / (float)(c > 1 ? c : 1);
                float4 r;
                r.x = (a0.x + a1.x + a2.x + a3.x) * inv;
                r.y = (a0.y + a1.y + a2.y + a3.y) * inv;
                r.z = (a0.z + a1.z + a2.z + a3.z) * inv;
                r.w = (a0.w + a1.w + a2.w + a3.w) * inv;
                float hx = __bfloat162float(__float2bfloat16(r.x));
                float hy = __bfloat162float(__float2bfloat16(r.y));
                float hz = __bfloat162float(__float2bfloat16(r.z));
                float hw = __bfloat162float(__float2bfloat16(r.w));
                uint2 hv, lv;
                hv.x = pack_bf16x2(r.y, r.x); hv.y = pack_bf16x2(r.w, r.z);
                lv.x = pack_bf16x2(r.y - hy, r.x - hx); lv.y = pack_bf16x2(r.w - hw, r.z - hz);
                uint32_t ro = (uint32_t)((wrow + rr) * AGG_STR + lane * 8);
                *(uint2*)(dsm + AGG_BASE + ro) = hv;
                *(uint2*)(dsm + AGG_BASE + AGG_IMG + ro) = lv;
            }
        }
        __syncthreads();   // agg smem ready for all warps

        float acc[2][8][4];
        #pragma unroll
        for (int mt = 0; mt < 2; mt++)
            #pragma unroll
            for (int nt = 0; nt < 8; nt++)
                #pragma unroll
                for (int q = 0; q < 4; q++) acc[mt][nt][q] = 0.f;

        #pragma unroll
        for (int c = 0; c < 4; c++) {
            CPW(0);
            __syncthreads();   // x chunk c (and W on first iter) resident

            #pragma unroll
            for (int ks = 0; ks < 2; ks++) {
                // A fragments: agg hi/lo from 272-stride, x hi/lo from 80B chunk
                uint32_t afr[4][2][4];
                #pragma unroll
                for (int ai = 0; ai < 2; ai++)
                    #pragma unroll
                    for (int mt = 0; mt < 2; mt++) {
                        uint32_t addr = agg_u32 + ai * AGG_IMG
                            + (uint32_t)((warp_m * 32 + mt * 16 + (lane & 15)) * AGG_STR)
                            + (uint32_t)((c * 4 + ks * 2 + (lane >> 4)) * 16);
                        ldsm4(afr[ai][mt], addr);
                    }
                #pragma unroll
                for (int ai = 0; ai < 2; ai++)
                    #pragma unroll
                    for (int mt = 0; mt < 2; mt++) {
                        uint32_t addr = x_u32 + ai * X_IMG
                            + (uint32_t)((warp_m * 32 + mt * 16 + (lane & 15)) * 80)
                            + (uint32_t)((ks * 2 + (lane >> 4)) * 16);
                        ldsm4(afr[2 + ai][mt], addr);
                    }
                #pragma unroll
                for (int wi = 0; wi < 4; wi++) {
                    uint32_t bfr[4][4];
                    #pragma unroll
                    for (int pr = 0; pr < 4; pr++) {
                        int n = warp_n * 64 + pr * 16 + (lane & 7) + ((lane >> 4) & 1) * 8;
                        int ck = c * 4 + ks * 2 + ((lane >> 3) & 1);
                        uint32_t addr = w_u32 + wi * 32768
                            + (uint32_t)(n * 256 + ((ck ^ (n & 7)) << 4));
                        ldsm4(bfr[pr], addr);
                    }
                    const int a0 = (wi < 2) ? 0 : 2;
                    #pragma unroll
                    for (int mt = 0; mt < 2; mt++)
                        #pragma unroll
                        for (int nt = 0; nt < 8; nt++)
                            mma16816(acc[mt][nt], afr[a0][mt],
                                     bfr[nt >> 1][(nt & 1) * 2], bfr[nt >> 1][(nt & 1) * 2 + 1]);
                    if ((wi & 1) == 0) {
                        #pragma unroll
                        for (int mt = 0; mt < 2; mt++)
                            #pragma unroll
                            for (int nt = 0; nt < 8; nt++)
                                mma16816(acc[mt][nt], afr[a0 + 1][mt],
                                         bfr[nt >> 1][(nt & 1) * 2], bfr[nt >> 1][(nt & 1) * 2 + 1]);
                    }
                }
            }
            __syncthreads();   // done reading x buffer

            if (c < 3) {
                const int kc = (c + 1) * 64;  // byte offset of k-slice
                #pragma unroll
                for (int j = 0; j < 4; j++) {
                    int ch = t + j * 256;       // < 1024
                    int img = ch >> 9, rem = ch & 511;
                    int row = rem >> 2, cc = rem & 3;
                    int rg = bm + row;
                    int ok = rg < NN;
                    const char* src = Ximg[img] + (size_t)(ok ? rg : 0) * 256 + kc + cc * 16;
                    CPA16(x_u32 + img * X_IMG + row * 80 + cc * 16, src, ok ? 16 : 0);
                }
                CPC();
            }
        }

        // epilogue: bias + leaky relu (+ residual), fp32 out + optional bf16 split out
        #pragma unroll
        for (int mt = 0; mt < 2; mt++) {
            #pragma unroll
            for (int nt = 0; nt < 8; nt++) {
                int col = warp_n * 64 + nt * 8 + (lane & 3) * 2;
                int r0 = bm + warp_m * 32 + mt * 16 + (lane >> 2);
                #pragma unroll
                for (int h = 0; h < 2; h++) {
                    int r = r0 + h * 8;
                    if (r < NN) {
                        float f0 = acc[mt][nt][2 * h + 0] + bv[nt].x;
                        float f1 = acc[mt][nt][2 * h + 1] + bv[nt].y;
                        f0 = f0 >= 0.f ? f0 : 0.01f * f0;
                        f1 = f1 >= 0.f ? f1 : 0.01f * f1;
                        if (resid) {
                            float2 xv = *(const float2*)(xF + (size_t)r * DD + col);
                            f0 += xv.x; f1 += xv.y;
                        }
                        float2 o; o.x = f0; o.y = f1;
                        *(float2*)(outF + (size_t)r * DD + col) = o;
                        if (wsplit) {
                            float h0 = __bfloat162float(__float2bfloat16(f0));
                            float h1 = __bfloat162float(__float2bfloat16(f1));
                            *(uint32_t*)(oH + (size_t)r * DD + col) = pack_bf16x2(f1, f0);
                            *(uint32_t*)(oL + (size_t)r * DD + col) = pack_bf16x2(f1 - h1, f0 - h0);
                        }
                    }
                }
            }
        }
        __syncthreads();   // agg smem reuse guard for next tile
    }
}

// ---------------- global mean pool per graph ----------------
__global__ void pool_kernel(const float* __restrict__ x, float* __restrict__ outp) {
    int g = blockIdx.x;
    int c = threadIdx.x & 127;
    int half = threadIdx.x >> 7;    // 0 or 1
    __shared__ int s_lo, s_hi;
    __shared__ float part[128];
    if (threadIdx.x == 0) {
        int lo = 0, hi = NN;
        while (lo < hi) { int mid = (lo + hi) >> 1; if (g_batch[mid] < g) lo = mid + 1; else hi = mid; }
        s_lo = lo;
        int lo2 = lo, hi2 = NN;
        while (lo2 < hi2) { int mid = (lo2 + hi2) >> 1; if (g_batch[mid] < g + 1) lo2 = mid + 1; else hi2 = mid; }
        s_hi = lo2;
    }
    __syncthreads();
    int lo = s_lo, hi = s_hi;
    float s0 = 0.f, s1 = 0.f, s2 = 0.f, s3 = 0.f;
    int r = lo + half * 4;
    for (; r + 4 <= hi; r += 8) {
        s0 += x[(r + 0) * DD + c];
        s1 += x[(r + 1) * DD + c];
        s2 += x[(r + 2) * DD + c];
        s3 += x[(r + 3) * DD + c];
    }
    for (; r < hi; ++r) s0 += x[r * DD + c];
    float mysum = s0 + s1 + s2 + s3;
    if (half == 1) part[c] = mysum;
    __syncthreads();
    if (half == 0) {
        float cnt = (float)(hi - lo);
        outp[g * DD + c] = (mysum + part[c]) / fmaxf(cnt, 1.0f);
    }
}

// ---------------- launch ----------------
extern "C" void kernel_launch(void* const* d_in, const int* in_sizes, int n_in,
                              void* d_out, int out_size) {
    const float* x_in = (const float*)d_in[0];
    const void* eidx  = d_in[1];
    const void* batch = d_in[2];
    const float* Wl   = (const float*)d_in[3];
    const float* bl   = (const float*)d_in[4];
    const float* Wr   = (const float*)d_in[5];
    float* outp = (float*)d_out;

    float *bufA, *bufB;
    __nv_bfloat16 *xH, *xL, *wimg;
    cudaGetSymbolAddress((void**)&bufA, g_bufA);
    cudaGetSymbolAddress((void**)&bufB, g_bufB);
    cudaGetSymbolAddress((void**)&xH,   g_xH);
    cudaGetSymbolAddress((void**)&xL,   g_xL);
    cudaGetSymbolAddress((void**)&wimg, g_Wimg);

    cudaFuncSetAttribute(fused_kernel, cudaFuncAttributeMaxDynamicSharedMemorySize, SMEM_TOTAL);

    const int NBLK = (NN + 1023) / 1024;   // 49
    splitw_kernel<<<512, 256>>>(Wl, Wr);
    splitx_kernel<<<6250, 256>>>((const float4*)x_in);
    zerodetect_kernel<<<196, 256>>>((const int*)eidx);
    convhist_kernel<<<(NE + 255) / 256, 256>>>(eidx, batch);
    scan1_kernel<<<NBLK, 1024>>>();
    scan23_kernel<<<NBLK, 1024>>>(NBLK);
    fill_kernel<<<(NE + 255) / 256, 256>>>();

    const float* cur = x_in;
    float* outs[4] = {bufA, bufB, bufA, bufB};
    for (int l = 0; l < 4; l++) {
        fused_kernel<<<148, 256, SMEM_TOTAL>>>(cur, xH, xL,
                                               wimg + l * 65536, bl + l * DD,
                                               outs[l], xH, xL,
                                               l >= 2 ? 1 : 0, l < 3 ? 1 : 0);
        cur = outs[l];
    }
    pool_kernel<<<64, 256>>>(cur, outp);
}

// round 14
// speedup vs baseline: 1.5541x; 1.5541x over previous
#include <cuda_runtime.h>
#include <cuda_bf16.h>
#include <cstdint>

#define NN 50000
#define NE 600000
#define DD 128
#define NG 64
#define NTILE 391

typedef unsigned long long u64;

// ---------------- device scratch (no allocations allowed) ----------------
__device__ float g_bufA[NN * DD];
__device__ float g_bufB[NN * DD];
__device__ __nv_bfloat16 g_aggH[NN * DD];
__device__ __nv_bfloat16 g_aggL[NN * DD];
__device__ __nv_bfloat16 g_xH[NN * DD];
__device__ __nv_bfloat16 g_xL[NN * DD];
__device__ int g_src[NE];
__device__ int g_dst[NE];
__device__ int g_csr[NE];
__device__ int g_cnt[NN];
__device__ int g_ofs[NN + 1];
__device__ int g_fill[NN];
__device__ int g_batch[NN];
__device__ int g_bsum[64];
// [layer][WlH, WlL, WrH, WrL], each image 16384 bf16, pre-swizzled for smem
__device__ __nv_bfloat16 g_Wimg[16 * 16384];
__device__ int g_flag;  // 1 => inputs are int32, 0 => int64 (monotone, deterministic)

__device__ __forceinline__ uint32_t smem_to_u32(const void* smem_ptr) {
    uint32_t addr;
    asm("{ .reg .u64 tmp; cvta.to.shared.u64 tmp, %1; cvt.u32.u64 %0, tmp; }"
        : "=r"(addr) : "l"(smem_ptr));
    return addr;
}
__device__ __forceinline__ uint32_t pack_bf16x2(float hi_elem, float lo_elem) {
    uint32_t r;
    asm("cvt.rn.bf16x2.f32 %0, %1, %2;" : "=r"(r) : "f"(hi_elem), "f"(lo_elem));
    return r;
}
__device__ __forceinline__ void ldsm4(uint32_t* r, uint32_t addr) {
    asm volatile("ldmatrix.sync.aligned.m8n8.x4.shared.b16 {%0,%1,%2,%3}, [%4];"
                 : "=r"(r[0]), "=r"(r[1]), "=r"(r[2]), "=r"(r[3]) : "r"(addr));
}
__device__ __forceinline__ void mma16816(float* c, const uint32_t* a, uint32_t b0, uint32_t b1) {
    asm volatile(
        "mma.sync.aligned.m16n8k16.row.col.f32.bf16.bf16.f32 "
        "{%0,%1,%2,%3}, {%4,%5,%6,%7}, {%8,%9}, {%0,%1,%2,%3};"
        : "+f"(c[0]), "+f"(c[1]), "+f"(c[2]), "+f"(c[3])
        : "r"(a[0]), "r"(a[1]), "r"(a[2]), "r"(a[3]), "r"(b0), "r"(b1));
}
#define CPA16(dst, src, sz) \
    asm volatile("cp.async.cg.shared.global [%0], [%1], 16, %2;" \
                 :: "r"(dst), "l"(src), "r"(sz) : "memory")
#define CPC() asm volatile("cp.async.commit_group;" ::: "memory")
#define CPW(n) asm volatile("cp.async.wait_group %0;" :: "n"(n) : "memory")

// ---------------- setup kernels ----------------
__global__ void splitw_kernel(const float* __restrict__ Wl, const float* __restrict__ Wr) {
    int i = blockIdx.x * blockDim.x + threadIdx.x;  // < 4*2*16384
    int l = i >> 15;
    int rem = i & 32767;
    int mat = rem >> 14;
    int nk = rem & 16383;
    int n = nk >> 7, k = nk & 127;
    const float* W = mat ? Wr : Wl;
    float v = W[l * 16384 + nk];
    __nv_bfloat16 bh = __float2bfloat16(v);
    float fhi = __bfloat162float(bh);
    __nv_bfloat16 blo = __float2bfloat16(v - fhi);
    int off = n * 128 + (((k >> 3) ^ (n & 7)) << 3) + (k & 7);
    int base = (l * 4 + mat * 2) * 16384;
    g_Wimg[base + off] = bh;
    g_Wimg[base + 16384 + off] = blo;
}

// Split x_in into bf16 hi/lo images; also zero counts and detect edge dtype.
__global__ void splitx_kernel(const float4* __restrict__ x, const int* __restrict__ e) {
    int i = blockIdx.x * blockDim.x + threadIdx.x;  // < NN*32
    if (i < NN) g_cnt[i] = 0;
    if (blockIdx.x == 0) {
        int nz = 0;
        for (int j = threadIdx.x; j < 4096; j += 256) nz |= e[2 * j + 1];
        if (nz) g_flag = 1;
    }
    if (i >= NN * 32) return;
    float4 f = x[i];
    float hx = __bfloat162float(__float2bfloat16(f.x));
    float hy = __bfloat162float(__float2bfloat16(f.y));
    float hz = __bfloat162float(__float2bfloat16(f.z));
    float hw = __bfloat162float(__float2bfloat16(f.w));
    uint2 hv, lv;
    hv.x = pack_bf16x2(f.y, f.x); hv.y = pack_bf16x2(f.w, f.z);
    lv.x = pack_bf16x2(f.y - hy, f.x - hx); lv.y = pack_bf16x2(f.w - hw, f.z - hz);
    ((uint2*)g_xH)[i] = hv;
    ((uint2*)g_xL)[i] = lv;
}

// convert edges + batch, and histogram dst degrees in one pass
__global__ void convhist_kernel(const void* __restrict__ e, const void* __restrict__ b) {
    int i = blockIdx.x * blockDim.x + threadIdx.x;
    int is32 = g_flag;
    if (i < NE) {
        int s, d;
        if (is32) {
            const int* p = (const int*)e;
            s = p[i]; d = p[NE + i];
        } else {
            const long long* p = (const long long*)e;
            s = (int)p[i]; d = (int)p[NE + i];
        }
        g_src[i] = s;
        g_dst[i] = d;
        atomicAdd(&g_cnt[d], 1);
    }
    if (i < NN) {
        g_batch[i] = is32 ? ((const int*)b)[i] : (int)((const long long*)b)[i];
    }
}

// ---- 2-pass grid-wide exclusive scan of g_cnt -> g_ofs / g_fill ----
__global__ void scan1_kernel() {
    __shared__ int wsum[32];
    int b = blockIdx.x, t = threadIdx.x;
    int idx = b * 1024 + t;
    int v = (idx < NN) ? g_cnt[idx] : 0;
    int lane = t & 31, wid = t >> 5;
    int x = v;
    #pragma unroll
    for (int d = 1; d < 32; d <<= 1) {
        int n = __shfl_up_sync(0xFFFFFFFFu, x, d);
        if (lane >= d) x += n;
    }
    if (lane == 31) wsum[wid] = x;
    __syncthreads();
    if (wid == 0) {
        int wv = wsum[lane];
        #pragma unroll
        for (int d = 1; d < 32; d <<= 1) {
            int n = __shfl_up_sync(0xFFFFFFFFu, wv, d);
            if (lane >= d) wv += n;
        }
        wsum[lane] = wv;
    }
    __syncthreads();
    int excl = (x - v) + (wid > 0 ? wsum[wid - 1] : 0);
    if (idx < NN) g_ofs[idx] = excl;
    if (t == 1023) g_bsum[b] = excl + v;  // block total
}

// pass 2: each block computes its own block offset from g_bsum and applies it.
__global__ void scan23_kernel(int nblk) {
    __shared__ int s_bsum[64];
    __shared__ int s_off;
    int b = blockIdx.x, t = threadIdx.x;
    if (t < nblk) s_bsum[t] = g_bsum[t];
    __syncthreads();
    if (t == 0) {
        int run = 0;
        for (int j = 0; j < b; j++) run += s_bsum[j];
        s_off = run;
        if (b == nblk - 1) {
            int tot = run;
            for (int j = b; j < nblk; j++) tot += s_bsum[j];
            g_ofs[NN] = tot;
        }
    }
    __syncthreads();
    int idx = b * 1024 + t;
    if (idx < NN) {
        int o = g_ofs[idx] + s_off;
        g_ofs[idx] = o;
        g_fill[idx] = o;
    }
}

__global__ void fill_kernel() {
    int i = blockIdx.x * blockDim.x + threadIdx.x;
    if (i < NE) {
        int d = g_dst[i];
        int pos = atomicAdd(&g_fill[d], 1);
        g_csr[pos] = g_src[i];
    }
}

// ---------------- mean aggregation: one warp per node, writes bf16 split ----------------
__global__ void agg_kernel(const float4* __restrict__ x) {
    int w = (blockIdx.x * 256 + threadIdx.x) >> 5;
    int lane = threadIdx.x & 31;
    int beg = g_ofs[w], end = g_ofs[w + 1];
    float4 a0 = make_float4(0.f, 0.f, 0.f, 0.f);
    float4 a1 = a0, a2 = a0, a3 = a0;
    int e = beg;
    for (; e + 4 <= end; e += 4) {
        int s0 = g_csr[e], s1 = g_csr[e + 1], s2 = g_csr[e + 2], s3 = g_csr[e + 3];
        float4 v0 = x[s0 * 32 + lane];
        float4 v1 = x[s1 * 32 + lane];
        float4 v2 = x[s2 * 32 + lane];
        float4 v3 = x[s3 * 32 + lane];
        a0.x += v0.x; a0.y += v0.y; a0.z += v0.z; a0.w += v0.w;
        a1.x += v1.x; a1.y += v1.y; a1.z += v1.z; a1.w += v1.w;
        a2.x += v2.x; a2.y += v2.y; a2.z += v2.z; a2.w += v2.w;
        a3.x += v3.x; a3.y += v3.y; a3.z += v3.z; a3.w += v3.w;
    }
    for (; e < end; e++) {
        int s = g_csr[e];
        float4 v = x[s * 32 + lane];
        a0.x += v.x; a0.y += v.y; a0.z += v.z; a0.w += v.w;
    }
    int c = end - beg;
    float inv = 1.0f / (float)(c > 1 ? c : 1);
    float4 r;
    r.x = (a0.x + a1.x + a2.x + a3.x) * inv;
    r.y = (a0.y + a1.y + a2.y + a3.y) * inv;
    r.z = (a0.z + a1.z + a2.z + a3.z) * inv;
    r.w = (a0.w + a1.w + a2.w + a3.w) * inv;
    float hx = __bfloat162float(__float2bfloat16(r.x));
    float hy = __bfloat162float(__float2bfloat16(r.y));
    float hz = __bfloat162float(__float2bfloat16(r.z));
    float hw = __bfloat162float(__float2bfloat16(r.w));
    uint2 hv, lv;
    hv.x = pack_bf16x2(r.y, r.x); hv.y = pack_bf16x2(r.w, r.z);
    lv.x = pack_bf16x2(r.y - hy, r.x - hx); lv.y = pack_bf16x2(r.w - hw, r.z - hz);
    ((uint2*)g_aggH)[w * 32 + lane] = hv;
    ((uint2*)g_aggL)[w * 32 + lane] = lv;
}

// ---------------- persistent mma.sync dual GEMM, cross-tile cp.async pipeline ----------------
// out[m][:] = act( agg[m]@Wl^T + x[m]@Wr^T + bias ) (+ x[m][:] if resid)
// smem: W images 4 x 32KB (swizzled) + A chunk buffers 2 x (4 imgs x 128 rows x 80B)
#define W_SM 131072
#define A_BUF 40960
#define SMEM_TOTAL (W_SM + 2 * A_BUF)   // 212992

// issue one A chunk (4 images x 128 rows x 64B = 2048 x 16B) for rows [bm_, bm_+128),
// k-slice byte offset kc_, into smem buffer buf_.
#define ISSUE_CHUNK(bm_, kc_, buf_) do { \
    _Pragma("unroll") \
    for (int j_ = 0; j_ < 8; j_++) { \
        int ch_ = t + j_ * 256; \
        int img_ = ch_ >> 9, rem_ = ch_ & 511; \
        int row_ = rem_ >> 2, cc_ = rem_ & 3; \
        int rg_ = (bm_) + row_; \
        int ok_ = rg_ < NN; \
        const char* src_ = Aimg[img_] + (size_t)(ok_ ? rg_ : 0) * 256 + (kc_) + cc_ * 16; \
        CPA16((buf_) + img_ * 10240 + row_ * 80 + cc_ * 16, src_, ok_ ? 16 : 0); \
    } \
} while (0)

__global__ __launch_bounds__(256, 1)
void mma_kernel(const __nv_bfloat16* __restrict__ aggH, const __nv_bfloat16* __restrict__ aggL,
                const __nv_bfloat16* __restrict__ xH, const __nv_bfloat16* __restrict__ xL,
                const __nv_bfloat16* __restrict__ Wimg, const float* __restrict__ bias,
                const float* __restrict__ xres, float* __restrict__ outp,
                __nv_bfloat16* __restrict__ oH, __nv_bfloat16* __restrict__ oL,
                int resid, int wsplit) {
    extern __shared__ __align__(16) char dsm[];
    char* Wsm = dsm;
    char* Abuf[2] = {dsm + W_SM, dsm + W_SM + A_BUF};

    const int t = threadIdx.x;
    const int lane = t & 31;
    const int wid = t >> 5;
    const int warp_m = wid >> 1;
    const int warp_n = wid & 1;
    const uint32_t w_u32 = smem_to_u32(Wsm);
    const uint32_t abuf_u32[2] = {smem_to_u32(Abuf[0]), smem_to_u32(Abuf[1])};

    const char* Aimg[4] = {(const char*)aggH, (const char*)aggL,
                           (const char*)xH, (const char*)xL};

    // bias per-thread registers (cols this thread owns)
    float2 bv[8];
    #pragma unroll
    for (int nt = 0; nt < 8; nt++)
        bv[nt] = *(const float2*)(bias + warp_n * 64 + nt * 8 + (lane & 3) * 2);

    // stage all 4 W images: 8192 linear 16B chunks (group 0)
    {
        const char* wp = (const char*)Wimg;
        #pragma unroll 8
        for (int i = t; i < 8192; i += 256)
            CPA16(w_u32 + i * 16, wp + i * 16, 16);
        CPC();
    }

    // prologue: issue chunk 0 of first tile into buf 0 (group 1)
    if ((int)blockIdx.x < NTILE) {
        ISSUE_CHUNK(blockIdx.x * 128, 0, abuf_u32[0]);
    }
    CPC();

    for (int tile = blockIdx.x; tile < NTILE; tile += gridDim.x) {
        const int bm = tile * 128;

        float acc[2][8][4];
        #pragma unroll
        for (int mt = 0; mt < 2; mt++)
            #pragma unroll
            for (int nt = 0; nt < 8; nt++)
                #pragma unroll
                for (int q = 0; q < 4; q++) acc[mt][nt][q] = 0.f;

        #pragma unroll
        for (int c = 0; c < 4; c++) {
            // issue next chunk (same tile c+1, or next tile's chunk 0); always commit
            {
                int ntile = (c < 3) ? tile : tile + (int)gridDim.x;
                int nc = (c < 3) ? c + 1 : 0;
                if (ntile < NTILE) {
                    ISSUE_CHUNK(ntile * 128, nc * 64, abuf_u32[(c + 1) & 1]);
                }
                CPC();
            }
            CPW(1);            // chunk c (and W on the very first wait) resident
            __syncthreads();

            const uint32_t ab = abuf_u32[c & 1];
            #pragma unroll
            for (int ks = 0; ks < 2; ks++) {
                uint32_t afr[4][2][4];
                #pragma unroll
                for (int ai = 0; ai < 4; ai++)
                    #pragma unroll
                    for (int mt = 0; mt < 2; mt++) {
                        uint32_t addr = ab + ai * 10240
                            + (uint32_t)((warp_m * 32 + mt * 16 + (lane & 15)) * 80)
                            + (uint32_t)((ks * 2 + (lane >> 4)) * 16);
                        ldsm4(afr[ai][mt], addr);
                    }
                #pragma unroll
                for (int wi = 0; wi < 4; wi++) {
                    uint32_t bfr[4][4];
                    #pragma unroll
                    for (int pr = 0; pr < 4; pr++) {
                        int n = warp_n * 64 + pr * 16 + (lane & 7) + ((lane >> 4) & 1) * 8;
                        int ck = c * 4 + ks * 2 + ((lane >> 3) & 1);
                        uint32_t addr = w_u32 + wi * 32768
                            + (uint32_t)(n * 256 + ((ck ^ (n & 7)) << 4));
                        ldsm4(bfr[pr], addr);
                    }
                    const int a0 = (wi < 2) ? 0 : 2;
                    #pragma unroll
                    for (int mt = 0; mt < 2; mt++)
                        #pragma unroll
                        for (int nt = 0; nt < 8; nt++)
                            mma16816(acc[mt][nt], afr[a0][mt],
                                     bfr[nt >> 1][(nt & 1) * 2], bfr[nt >> 1][(nt & 1) * 2 + 1]);
                    if ((wi & 1) == 0) {
                        #pragma unroll
                        for (int mt = 0; mt < 2; mt++)
                            #pragma unroll
                            for (int nt = 0; nt < 8; nt++)
                                mma16816(acc[mt][nt], afr[a0 + 1][mt],
                                         bfr[nt >> 1][(nt & 1) * 2], bfr[nt >> 1][(nt & 1) * 2 + 1]);
                    }
                }
            }
            __syncthreads();   // all warps done reading buf (c&1) before it is rewritten
        }

        // epilogue (overlaps next tile's chunk-0 load): bias + leaky relu (+ residual)
        #pragma unroll
        for (int mt = 0; mt < 2; mt++) {
            #pragma unroll
            for (int nt = 0; nt < 8; nt++) {
                int col = warp_n * 64 + nt * 8 + (lane & 3) * 2;
                int r0 = bm + warp_m * 32 + mt * 16 + (lane >> 2);
                #pragma unroll
                for (int h = 0; h < 2; h++) {
                    int r = r0 + h * 8;
                    if (r < NN) {
                        float f0 = acc[mt][nt][2 * h + 0] + bv[nt].x;
                        float f1 = acc[mt][nt][2 * h + 1] + bv[nt].y;
                        f0 = f0 >= 0.f ? f0 : 0.01f * f0;
                        f1 = f1 >= 0.f ? f1 : 0.01f * f1;
                        if (resid) {
                            float2 xv = *(const float2*)(xres + (size_t)r * DD + col);
                            f0 += xv.x; f1 += xv.y;
                        }
                        float2 o; o.x = f0; o.y = f1;
                        *(float2*)(outp + (size_t)r * DD + col) = o;
                        if (wsplit) {
                            float h0 = __bfloat162float(__float2bfloat16(f0));
                            float h1 = __bfloat162float(__float2bfloat16(f1));
                            *(uint32_t*)(oH + (size_t)r * DD + col) = pack_bf16x2(f1, f0);
                            *(uint32_t*)(oL + (size_t)r * DD + col) = pack_bf16x2(f1 - h1, f0 - h0);
                        }
                    }
                }
            }
        }
    }
}

// ---------------- global mean pool per graph ----------------
__global__ void pool_kernel(const float* __restrict__ x, float* __restrict__ outp) {
    int g = blockIdx.x;
    int c = threadIdx.x & 127;
    int half = threadIdx.x >> 7;    // 0 or 1
    __shared__ int s_lo, s_hi;
    __shared__ float part[128];
    if (threadIdx.x == 0) {
        int lo = 0, hi = NN;
        while (lo < hi) { int mid = (lo + hi) >> 1; if (g_batch[mid] < g) lo = mid + 1; else hi = mid; }
        s_lo = lo;
        int lo2 = lo, hi2 = NN;
        while (lo2 < hi2) { int mid = (lo2 + hi2) >> 1; if (g_batch[mid] < g + 1) lo2 = mid + 1; else hi2 = mid; }
        s_hi = lo2;
    }
    __syncthreads();
    int lo = s_lo, hi = s_hi;
    float s0 = 0.f, s1 = 0.f, s2 = 0.f, s3 = 0.f;
    int r = lo + half * 4;
    for (; r + 4 <= hi; r += 8) {
        s0 += x[(r + 0) * DD + c];
        s1 += x[(r + 1) * DD + c];
        s2 += x[(r + 2) * DD + c];
        s3 += x[(r + 3) * DD + c];
    }
    for (; r < hi; ++r) s0 += x[r * DD + c];
    float mysum = s0 + s1 + s2 + s3;
    if (half == 1) part[c] = mysum;
    __syncthreads();
    if (half == 0) {
        float cnt = (float)(hi - lo);
        outp[g * DD + c] = (mysum + part[c]) / fmaxf(cnt, 1.0f);
    }
}

// ---------------- launch ----------------
extern "C" void kernel_launch(void* const* d_in, const int* in_sizes, int n_in,
                              void* d_out, int out_size) {
    const float* x_in = (const float*)d_in[0];
    const void* eidx  = d_in[1];
    const void* batch = d_in[2];
    const float* Wl   = (const float*)d_in[3];
    const float* bl   = (const float*)d_in[4];
    const float* Wr   = (const float*)d_in[5];
    float* outp = (float*)d_out;

    float *bufA, *bufB;
    __nv_bfloat16 *aggH, *aggL, *xH, *xL, *wimg;
    cudaGetSymbolAddress((void**)&bufA, g_bufA);
    cudaGetSymbolAddress((void**)&bufB, g_bufB);
    cudaGetSymbolAddress((void**)&aggH, g_aggH);
    cudaGetSymbolAddress((void**)&aggL, g_aggL);
    cudaGetSymbolAddress((void**)&xH,   g_xH);
    cudaGetSymbolAddress((void**)&xL,   g_xL);
    cudaGetSymbolAddress((void**)&wimg, g_Wimg);

    cudaFuncSetAttribute(mma_kernel, cudaFuncAttributeMaxDynamicSharedMemorySize, SMEM_TOTAL);

    const int NBLK = (NN + 1023) / 1024;   // 49
    splitw_kernel<<<512, 256>>>(Wl, Wr);
    splitx_kernel<<<6250, 256>>>((const float4*)x_in, (const int*)eidx);
    convhist_kernel<<<(NE + 255) / 256, 256>>>(eidx, batch);
    scan1_kernel<<<NBLK, 1024>>>();
    scan23_kernel<<<NBLK, 1024>>>(NBLK);
    fill_kernel<<<(NE + 255) / 256, 256>>>();

    const float* cur = x_in;
    float* outs[4] = {bufA, bufB, bufA, bufB};
    for (int l = 0; l < 4; l++) {
        agg_kernel<<<6250, 256>>>((const float4*)cur);
        mma_kernel<<<148, 256, SMEM_TOTAL>>>(aggH, aggL, xH, xL,
                                             wimg + l * 65536, bl + l * DD,
                                             cur, outs[l], xH, xL,
                                             l >= 2 ? 1 : 0, l < 3 ? 1 : 0);
        cur = outs[l];
    }
    pool_kernel<<<64, 256>>>(cur, outp);
}